// round 12
// baseline (speedup 1.0000x reference)
#include <cuda_runtime.h>
#include <cuda_bf16.h>
#include <cstdint>

#define DI __device__ __forceinline__

static constexpr int GROUPS = 8, MTOK = 2048, HID = 1024, INTER = 4096;

// ---------------------------------------------------------------------------
// Data layout for bf16 split planes: for a logical fp32 matrix [R, K] we store
// rows as consecutive 32-k blocks of 128 bytes: [32 x bf16 hi | 32 x bf16 lo].
// Row r occupies (K/32)*128 bytes contiguously. This gives 128B rows -> SW128
// swizzle in SMEM, conflict-free for both cp.async 16B stores and ldmatrix.
// ---------------------------------------------------------------------------

// ------------------------- device scratch (split planes) -------------------
__device__ __nv_bfloat16 g_x [(size_t)GROUPS * MTOK * HID * 2];
__device__ __nv_bfloat16 g_w1[(size_t)GROUPS * INTER * HID * 2];
__device__ __nv_bfloat16 g_w2[(size_t)GROUPS * HID * INTER * 2];
__device__ __nv_bfloat16 g_h1[(size_t)GROUPS * MTOK * INTER * 2];

// ------------------------------ helpers ------------------------------------
DI uint32_t smem_u32(const void* p) {
    uint32_t a;
    asm("{ .reg .u64 t; cvta.to.shared.u64 t, %1; cvt.u32.u64 %0, t; }" : "=r"(a) : "l"(p));
    return a;
}
DI uint32_t swz(uint32_t off) { return off ^ ((off >> 3) & 0x70); }

DI void cp16(uint32_t s, const void* g) {
    asm volatile("cp.async.cg.shared.global [%0], [%1], 16;"
                 :: "r"(s), "l"(__cvta_generic_to_global(g)) : "memory");
}
DI void cp_commit() { asm volatile("cp.async.commit_group;" ::: "memory"); }

DI void ldm4(uint32_t* r, uint32_t addr) {
    asm volatile("ldmatrix.sync.aligned.m8n8.x4.shared.b16 {%0,%1,%2,%3}, [%4];"
                 : "=r"(r[0]), "=r"(r[1]), "=r"(r[2]), "=r"(r[3]) : "r"(addr));
}
DI void mma_bf16(float* d, const uint32_t* a, const uint32_t* b) {
    asm volatile(
        "mma.sync.aligned.m16n8k16.row.col.f32.bf16.bf16.f32 "
        "{%0,%1,%2,%3}, {%4,%5,%6,%7}, {%8,%9}, {%0,%1,%2,%3};"
        : "+f"(d[0]), "+f"(d[1]), "+f"(d[2]), "+f"(d[3])
        : "r"(a[0]), "r"(a[1]), "r"(a[2]), "r"(a[3]), "r"(b[0]), "r"(b[1]));
}

DI uint32_t pack2bf(float a, float b) {
    __nv_bfloat16 ha = __float2bfloat16_rn(a), hb = __float2bfloat16_rn(b);
    return (uint32_t)__bfloat16_as_ushort(ha) | ((uint32_t)__bfloat16_as_ushort(hb) << 16);
}
DI uint32_t packsplit(float a, float b, float& ra, float& rb) {
    __nv_bfloat16 ha = __float2bfloat16_rn(a), hb = __float2bfloat16_rn(b);
    ra = a - __bfloat162float(ha);
    rb = b - __bfloat162float(hb);
    return (uint32_t)__bfloat16_as_ushort(ha) | ((uint32_t)__bfloat16_as_ushort(hb) << 16);
}

// ------------------------------ split prep ---------------------------------
// Convert fp32 [R, K] into the interleaved hi/lo bf16 block layout.
// Each thread handles one float4 (4 consecutive k).
template <int T>  // 0 -> x (K=HID), 1 -> W1 (K=HID), 2 -> W2 (K=INTER)
__global__ void split_kernel(const float4* __restrict__ src, int n4, int K) {
    __nv_bfloat16* dst = (T == 0) ? g_x : ((T == 1) ? g_w1 : g_w2);
    int i = blockIdx.x * 256 + threadIdx.x;
    if (i >= n4) return;
    float4 v = src[i];
    float r0, r1, r2, r3;
    uint32_t h01 = packsplit(v.x, v.y, r0, r1);
    uint32_t h23 = packsplit(v.z, v.w, r2, r3);
    uint32_t l01 = pack2bf(r0, r1);
    uint32_t l23 = pack2bf(r2, r3);
    int f0 = i * 4;
    int r = f0 / K, k = f0 % K;
    int kb = k >> 5, ko = k & 31;
    size_t base = ((size_t)r * (K >> 5) + kb) * 64;  // bf16 elems
    *reinterpret_cast<uint2*>(dst + base + ko)      = make_uint2(h01, h23);
    *reinterpret_cast<uint2*>(dst + base + 32 + ko) = make_uint2(l01, l23);
}

// ------------------------------ GEMM kernel ---------------------------------
// CTA tile 128(M) x 128(N), BK = 32 k per stage (one 128B block per row).
// SMEM stage: A 128 rows x 128B = 16KB, B 16KB -> 32KB. 6 stages = 192KB.
// 8 warps: wm = w&1 (M), wn = w>>1 (N). Warp tile 64x32.
// MODE 0: h1 = x @ W1^T + b1  -> split-layout g_h1
// MODE 1: out = h1 @ W2^T + b2 -> fp32 d_out
static constexpr int NSTAGE = 6;
static constexpr uint32_t STG_BYTES = 32768;
static constexpr uint32_t SMEM_DYN = NSTAGE * STG_BYTES;

template <int MODE>
__global__ __launch_bounds__(256, 1) void gemm_kernel(const float* __restrict__ bias,
                                                      float* __restrict__ outp) {
    constexpr int K = (MODE == 0) ? HID : INTER;
    constexpr int N = (MODE == 0) ? INTER : HID;
    constexpr int NST = K / 32;
    constexpr long STRIDE_A = (long)(K / 32) * 128;  // bytes per A row
    constexpr long STRIDE_B = STRIDE_A;              // B rows have same K

    const int gB = blockIdx.z;
    const int mbase = blockIdx.y * 128;
    const int nbase = blockIdx.x * 128;
    const int t = threadIdx.x;
    const int lane = t & 31, w = t >> 5;
    const int wm = w & 1, wn = w >> 1;

    const char* Abase = reinterpret_cast<const char*>((MODE == 0) ? g_x : g_h1)
                      + ((size_t)gB * MTOK + mbase) * STRIDE_A;
    const char* Bbase = reinterpret_cast<const char*>((MODE == 0) ? g_w1 : g_w2)
                      + ((size_t)gB * N + nbase) * STRIDE_B;

    extern __shared__ char smem[];
    const uint32_t sb = smem_u32(smem);

    // ldmatrix per-lane address components
    const int rowA = (lane & 7) + ((lane >> 3) & 1) * 8;
    const int kA   = (lane >> 4) * 8;                    // 0 or 8
    const int rowB = (lane & 7) + ((lane >> 4) & 1) * 8;
    const int kB   = ((lane >> 3) & 1) * 8;
    const uint32_t offA0 = (uint32_t)((wm * 64 + rowA) * 128 + kA * 2);
    const uint32_t offB0 = (uint32_t)((wn * 32 + rowB) * 128 + kB * 2);

    float d[4][4][4];
    #pragma unroll
    for (int a = 0; a < 4; a++)
        #pragma unroll
        for (int b = 0; b < 4; b++)
            #pragma unroll
            for (int c = 0; c < 4; c++) d[a][b][c] = 0.f;

    // loader lambda-free: each thread moves 4 A-chunks + 4 B-chunks per stage
    auto load_stage = [&](int s) {
        const uint32_t dst = sb + (uint32_t)(s % NSTAGE) * STG_BYTES;
        const char* As = Abase + (size_t)s * 128;
        const char* Bs = Bbase + (size_t)s * 128;
        #pragma unroll
        for (int i = 0; i < 4; i++) {
            int q = t + 256 * i;
            int row = q >> 3, cb = (q & 7) * 16;
            uint32_t so = swz((uint32_t)(row * 128 + cb));
            cp16(dst + so,         As + (size_t)row * STRIDE_A + cb);
            cp16(dst + 16384 + so, Bs + (size_t)row * STRIDE_B + cb);
        }
        cp_commit();
    };

    // prologue: stages 0..4
    #pragma unroll
    for (int s = 0; s < NSTAGE - 1; s++) load_stage(s);

    for (int ks = 0; ks < NST; ks++) {
        asm volatile("cp.async.wait_group 4;" ::: "memory");  // stage ks arrived
        __syncthreads();
        if (ks + NSTAGE - 1 < NST) load_stage(ks + NSTAGE - 1);
        else cp_commit();  // keep group count consistent

        const uint32_t ab = sb + (uint32_t)(ks % NSTAGE) * STG_BYTES;
        const uint32_t bb = ab + 16384;

        #pragma unroll
        for (int ki = 0; ki < 2; ki++) {
            uint32_t ah[4][4], al[4][4];   // A frags per m-tile, hi/lo
            uint32_t bh[2][4], bl[2][4];   // B frags per n-tile-pair, hi/lo
            #pragma unroll
            for (int mt = 0; mt < 4; mt++) {
                uint32_t o = offA0 + (uint32_t)(mt * 2048 + ki * 32);
                ldm4(ah[mt], ab + swz(o));
                ldm4(al[mt], ab + swz(o + 64));
            }
            #pragma unroll
            for (int np = 0; np < 2; np++) {
                uint32_t o = offB0 + (uint32_t)(np * 2048 + ki * 32);
                ldm4(bh[np], bb + swz(o));
                ldm4(bl[np], bb + swz(o + 64));
            }
            #pragma unroll
            for (int mt = 0; mt < 4; mt++)
                #pragma unroll
                for (int nt = 0; nt < 4; nt++) {
                    const int np = nt >> 1, sel = (nt & 1) * 2;
                    mma_bf16(d[mt][nt], ah[mt], &bh[np][sel]);
                    mma_bf16(d[mt][nt], ah[mt], &bl[np][sel]);
                    mma_bf16(d[mt][nt], al[mt], &bh[np][sel]);
                }
        }
    }

    // ------------------------------ epilogue --------------------------------
    const int g = lane >> 2, tg = lane & 3;
    const float* bs = bias + (size_t)gB * N;
    #pragma unroll
    for (int mt = 0; mt < 4; mt++) {
        #pragma unroll
        for (int half = 0; half < 2; half++) {
            const int mrow = mbase + wm * 64 + mt * 16 + g + half * 8;
            #pragma unroll
            for (int nt = 0; nt < 4; nt++) {
                const int col = nbase + wn * 32 + nt * 8 + 2 * tg;
                float v0 = d[mt][nt][half * 2 + 0] + bs[col];
                float v1 = d[mt][nt][half * 2 + 1] + bs[col + 1];
                if (MODE == 0) {
                    float r0, r1;
                    uint32_t hi = packsplit(v0, v1, r0, r1);
                    uint32_t lo = pack2bf(r0, r1);
                    const int ko = nt * 8 + 2 * tg + (wn & 1) * 32;  // col % 32? see below
                    // col within its 32-block: (col % 32)
                    const int ko32 = col & 31;
                    size_t base = ((size_t)(gB * MTOK + mrow) * (INTER >> 5) + (col >> 5)) * 64;
                    (void)ko;
                    *reinterpret_cast<uint32_t*>(g_h1 + base + ko32)      = hi;
                    *reinterpret_cast<uint32_t*>(g_h1 + base + 32 + ko32) = lo;
                } else {
                    float2 o2 = make_float2(v0, v1);
                    *reinterpret_cast<float2*>(outp + ((size_t)gB * MTOK + mrow) * N + col) = o2;
                }
            }
        }
    }
}

// ------------------------------ launch ---------------------------------
extern "C" void kernel_launch(void* const* d_in, const int* in_sizes, int n_in,
                              void* d_out, int out_size) {
    const float *x = nullptr, *W1 = nullptr, *b1 = nullptr, *W2 = nullptr, *b2 = nullptr;
    for (int i = 0; i < n_in; i++) {
        const int s = in_sizes[i];
        if (s == GROUPS * MTOK * HID)        x = (const float*)d_in[i];
        else if (s == GROUPS * INTER * HID) { if (!W1) W1 = (const float*)d_in[i];
                                              else      W2 = (const float*)d_in[i]; }
        else if (s == GROUPS * INTER)        b1 = (const float*)d_in[i];
        else if (s == GROUPS * HID)          b2 = (const float*)d_in[i];
    }

    cudaFuncSetAttribute(gemm_kernel<0>, cudaFuncAttributeMaxDynamicSharedMemorySize, SMEM_DYN);
    cudaFuncSetAttribute(gemm_kernel<1>, cudaFuncAttributeMaxDynamicSharedMemorySize, SMEM_DYN);

    // 1) split fp32 inputs into interleaved hi/lo bf16 block layout
    {
        int n4x = GROUPS * MTOK * HID / 4;
        split_kernel<0><<<(n4x + 255) / 256, 256>>>((const float4*)x, n4x, HID);
        int n4w = GROUPS * INTER * HID / 4;
        split_kernel<1><<<(n4w + 255) / 256, 256>>>((const float4*)W1, n4w, HID);
        split_kernel<2><<<(n4w + 255) / 256, 256>>>((const float4*)W2, n4w, INTER);
    }

    // 2) GEMM1: h1 = x @ W1^T + b1  (M=2048, N=4096, K=1024 per group)
    {
        dim3 grid(INTER / 128, MTOK / 128, GROUPS);
        gemm_kernel<0><<<grid, 256, SMEM_DYN>>>(b1, nullptr);
    }

    // 3) GEMM2: out = h1 @ W2^T + b2 (M=2048, N=1024, K=4096 per group)
    {
        dim3 grid(HID / 128, MTOK / 128, GROUPS);
        gemm_kernel<1><<<grid, 256, SMEM_DYN>>>(b2, (float*)d_out);
    }
}